// round 12
// baseline (speedup 1.0000x reference)
#include <cuda_runtime.h>
#include <cuda_bf16.h>
#include <math.h>
#include <stdint.h>

#define BATCH 2048
#define INPUT_DIM 256
#define UNITS 1024
#define KTOT (INPUT_DIM + UNITS)       // 1280
#define NGATE (4 * UNITS)              // 4096
#define STEPS 96
#define OUT_UNITS 256
#define OUT_ROW_STRIDE (STEPS * OUT_UNITS)  // 24576

// ---------------- persistent device scratch (__device__ globals only) ------
__device__ __nv_bfloat16 g_Wg_hi[NGATE * KTOT];   // gate weights, n-major [n'=4u+g][k]
__device__ __nv_bfloat16 g_Wg_lo[NGATE * KTOT];
__device__ __nv_bfloat16 g_Wdt_hi[OUT_UNITS * UNITS];  // proj weights, n-major [n][k]
__device__ __nv_bfloat16 g_Wdt_lo[OUT_UNITS * UNITS];
__device__ float g_bias_r[NGATE];                 // bias reordered to n'=4u+g
// double-buffered activations: cols 0-255 = x, 256..1279 = h
__device__ __nv_bfloat16 g_xh_hi[2][BATCH * KTOT];
__device__ __nv_bfloat16 g_xh_lo[2][BATCH * KTOT];
__device__ float g_c[BATCH * UNITS];

// ---------------- helpers ---------------------------------------------------
__device__ __forceinline__ uint32_t smaddr(const void* p) {
    return (uint32_t)__cvta_generic_to_shared(p);
}
__device__ __forceinline__ void cpa16(uint32_t dst, const void* src) {
    asm volatile("cp.async.cg.shared.global [%0], [%1], 16;\n" :: "r"(dst), "l"(src));
}
__device__ __forceinline__ void cp_commit() { asm volatile("cp.async.commit_group;\n"); }
__device__ __forceinline__ uint32_t ld32s(const __nv_bfloat16* p) {
    return *reinterpret_cast<const uint32_t*>(p);
}
__device__ __forceinline__ void mma_bf16(float* d, const uint32_t* a, const uint32_t* b) {
    asm volatile(
        "mma.sync.aligned.m16n8k16.row.col.f32.bf16.bf16.f32 "
        "{%0,%1,%2,%3},{%4,%5,%6,%7},{%8,%9},{%0,%1,%2,%3};\n"
        : "+f"(d[0]), "+f"(d[1]), "+f"(d[2]), "+f"(d[3])
        : "r"(a[0]), "r"(a[1]), "r"(a[2]), "r"(a[3]), "r"(b[0]), "r"(b[1]));
}
__device__ __forceinline__ void split_bf16(float v, __nv_bfloat16* hi, __nv_bfloat16* lo) {
    __nv_bfloat16 h = __float2bfloat16(v);
    *hi = h;
    *lo = __float2bfloat16(v - __bfloat162float(h));
}

// ---------------- prep kernels (run once per launch; deterministic) ---------
__global__ __launch_bounds__(256) void prep_gate_weights(
    const float* __restrict__ Wk, const float* __restrict__ Wr)
{
    int id = blockIdx.x * 256 + threadIdx.x;            // [n'][k]
    if (id >= NGATE * KTOT) return;
    int np = id / KTOT, k = id % KTOT;
    int u = np >> 2, gg = np & 3;
    int col = gg * UNITS + u;
    float w = (k < INPUT_DIM) ? Wk[k * NGATE + col] : Wr[(k - INPUT_DIM) * NGATE + col];
    split_bf16(w, &g_Wg_hi[id], &g_Wg_lo[id]);
}

__global__ __launch_bounds__(256) void prep_proj_weights(const float* __restrict__ Wd)
{
    int id = blockIdx.x * 256 + threadIdx.x;            // [n][k]
    if (id >= OUT_UNITS * UNITS) return;
    int n = id / UNITS, k = id % UNITS;
    float w = Wd[k * OUT_UNITS + n];
    split_bf16(w, &g_Wdt_hi[id], &g_Wdt_lo[id]);
}

__global__ __launch_bounds__(256) void prep_bias(const float* __restrict__ b)
{
    int id = blockIdx.x * 256 + threadIdx.x;
    if (id >= NGATE) return;
    int u = id >> 2, gg = id & 3;
    g_bias_r[id] = b[gg * UNITS + u];
}

__global__ __launch_bounds__(256) void prep_x(const float* __restrict__ x)
{
    int id = blockIdx.x * 256 + threadIdx.x;            // 2048*256
    if (id >= BATCH * INPUT_DIM) return;
    int bb = id >> 8, c = id & 255;
    split_bf16(x[id], &g_xh_hi[0][bb * KTOT + c], &g_xh_lo[0][bb * KTOT + c]);
}

__global__ __launch_bounds__(256) void prep_h(const float* __restrict__ h0)
{
    int id = blockIdx.x * 256 + threadIdx.x;            // 2048*1024
    if (id >= BATCH * UNITS) return;
    int bb = id >> 10, u = id & 1023;
    split_bf16(h0[id], &g_xh_hi[0][bb * KTOT + INPUT_DIM + u],
                       &g_xh_lo[0][bb * KTOT + INPUT_DIM + u]);
}

// ---------------- gates GEMM + fused LSTM cell ------------------------------
// z = xh_in @ Wg' (M=2048, N=4096, K=1280); per-thread lane pairs t^1 hold
// (zi,zf)/(zg,zo) for the same (row, unit) -> shfl exchange -> cell update.
// Writes c (in place) and h (split bf16) into xh_out. No z round-trip.
// block 128x128, 8 warps (4m x 2n), 3-stage cp.async ring, 1 sync/iter.
__global__ __launch_bounds__(256) void gates_mma(
    const __nv_bfloat16* __restrict__ xh_hi_in,
    const __nv_bfloat16* __restrict__ xh_lo_in,
    __nv_bfloat16* __restrict__ xh_hi_out,
    __nv_bfloat16* __restrict__ xh_lo_out,
    const float* __restrict__ c_in)
{
    __shared__ __nv_bfloat16 sA[3][2][128][16];   // [stage][hi/lo][m][k]
    __shared__ __nv_bfloat16 sB[3][2][128][16];   // [stage][hi/lo][n][k]

    const int tid = threadIdx.x;
    const int wid = tid >> 5, lane = tid & 31;
    const int g = lane >> 2, t = lane & 3;
    const int m0 = blockIdx.x * 128, n0 = blockIdx.y * 128;
    const int wm = (wid >> 1) * 32, wn = (wid & 1) * 64;

    const int row = tid >> 1;              // 0..127
    const int half = (tid & 1) * 8;        // element offset within 16-wide k slab
    const __nv_bfloat16* gAh = xh_hi_in + (size_t)(m0 + row) * KTOT + half;
    const __nv_bfloat16* gAl = xh_lo_in + (size_t)(m0 + row) * KTOT + half;
    const __nv_bfloat16* gBh = g_Wg_hi + (size_t)(n0 + row) * KTOT + half;
    const __nv_bfloat16* gBl = g_Wg_lo + (size_t)(n0 + row) * KTOT + half;

    float acc[2][8][4];
#pragma unroll
    for (int i = 0; i < 2; i++)
#pragma unroll
        for (int j = 0; j < 8; j++)
#pragma unroll
            for (int l = 0; l < 4; l++) acc[i][j][l] = 0.0f;

    const int NS = KTOT / 16;   // 80
    // prologue: stages 0,1
#pragma unroll
    for (int p = 0; p < 2; p++) {
        int kt = p * 16;
        cpa16(smaddr(&sA[p][0][row][half]), gAh + kt);
        cpa16(smaddr(&sA[p][1][row][half]), gAl + kt);
        cpa16(smaddr(&sB[p][0][row][half]), gBh + kt);
        cpa16(smaddr(&sB[p][1][row][half]), gBl + kt);
        cp_commit();
    }

    for (int s = 0; s < NS; s++) {
        asm volatile("cp.async.wait_group 1;\n");   // stage s complete
        __syncthreads();                            // ring reuse + visibility

        // prefetch stage s+2 (overwrites buffer (s-1)%3, now safe)
        if (s + 2 < NS) {
            int ps = (s + 2) % 3, kt = (s + 2) * 16;
            cpa16(smaddr(&sA[ps][0][row][half]), gAh + kt);
            cpa16(smaddr(&sA[ps][1][row][half]), gAl + kt);
            cpa16(smaddr(&sB[ps][0][row][half]), gBh + kt);
            cpa16(smaddr(&sB[ps][1][row][half]), gBl + kt);
        }
        cp_commit();   // always commit (empty groups keep the count aligned)

        const int st = s % 3;
        uint32_t ah[2][4], al[2][4];
#pragma unroll
        for (int mt = 0; mt < 2; mt++) {
            int mr = wm + mt * 16;
            ah[mt][0] = ld32s(&sA[st][0][mr + g][2 * t]);
            ah[mt][1] = ld32s(&sA[st][0][mr + g + 8][2 * t]);
            ah[mt][2] = ld32s(&sA[st][0][mr + g][2 * t + 8]);
            ah[mt][3] = ld32s(&sA[st][0][mr + g + 8][2 * t + 8]);
            al[mt][0] = ld32s(&sA[st][1][mr + g][2 * t]);
            al[mt][1] = ld32s(&sA[st][1][mr + g + 8][2 * t]);
            al[mt][2] = ld32s(&sA[st][1][mr + g][2 * t + 8]);
            al[mt][3] = ld32s(&sA[st][1][mr + g + 8][2 * t + 8]);
        }
#pragma unroll
        for (int nt = 0; nt < 8; nt++) {
            int nr = wn + nt * 8 + g;
            uint32_t bh[2], bl[2];
            bh[0] = ld32s(&sB[st][0][nr][2 * t]);
            bh[1] = ld32s(&sB[st][0][nr][2 * t + 8]);
            bl[0] = ld32s(&sB[st][1][nr][2 * t]);
            bl[1] = ld32s(&sB[st][1][nr][2 * t + 8]);
#pragma unroll
            for (int mt = 0; mt < 2; mt++) {
                mma_bf16(acc[mt][nt], ah[mt], bh);
                mma_bf16(acc[mt][nt], ah[mt], bl);
                mma_bf16(acc[mt][nt], al[mt], bh);
            }
        }
    }

    // ---- fused LSTM cell epilogue ----
    // lane t even holds (zi,zf), lane t^1 holds (zg,zo) for the same (m,u).
#pragma unroll
    for (int mt = 0; mt < 2; mt++) {
#pragma unroll
        for (int nt = 0; nt < 8; nt++) {
            float o0 = __shfl_xor_sync(0xffffffffu, acc[mt][nt][0], 1);
            float o1 = __shfl_xor_sync(0xffffffffu, acc[mt][nt][1], 1);
            float o2 = __shfl_xor_sync(0xffffffffu, acc[mt][nt][2], 1);
            float o3 = __shfl_xor_sync(0xffffffffu, acc[mt][nt][3], 1);
            if ((t & 1) == 0) {
                int n = n0 + wn + nt * 8 + 2 * t;   // multiple of 4
                int u = n >> 2;
                float4 b4 = *(const float4*)&g_bias_r[n];
                int m = m0 + wm + mt * 16 + g;
#pragma unroll
                for (int rh = 0; rh < 2; rh++) {
                    int mm = m + rh * 8;
                    float zi = acc[mt][nt][rh * 2 + 0] + b4.x;
                    float zf = acc[mt][nt][rh * 2 + 1] + b4.y;
                    float zg = (rh ? o2 : o0) + b4.z;
                    float zo = (rh ? o3 : o1) + b4.w;
                    float ii = 1.0f / (1.0f + expf(-zi));
                    float ff = 1.0f / (1.0f + expf(-zf));
                    float oo = 1.0f / (1.0f + expf(-zo));
                    float cn = ff * c_in[mm * UNITS + u] + ii * tanhf(zg);
                    float hn = oo * tanhf(cn);
                    g_c[mm * UNITS + u] = cn;
                    split_bf16(hn, &xh_hi_out[(size_t)mm * KTOT + INPUT_DIM + u],
                                   &xh_lo_out[(size_t)mm * KTOT + INPUT_DIM + u]);
                }
            }
        }
    }
}

// ---------------- projection: pred = h @ Wd + bd (M=2048, N=256, K=1024) ----
// block 64x64, 4 warps (2m x 2n). Writes fp32 out + bf16 next-x into xh buf.
__global__ __launch_bounds__(128) void proj_mma(
    const __nv_bfloat16* __restrict__ xh_hi,   // buffer holding h(t) (and next x)
    const __nv_bfloat16* __restrict__ xh_lo,
    __nv_bfloat16* __restrict__ xh_hi_out,     // same buffer, x region
    __nv_bfloat16* __restrict__ xh_lo_out,
    const float* __restrict__ bd,
    float* __restrict__ out_t)
{
    __shared__ __nv_bfloat16 sA[3][2][64][16];
    __shared__ __nv_bfloat16 sB[3][2][64][16];

    const int tid = threadIdx.x;
    const int wid = tid >> 5, lane = tid & 31;
    const int g = lane >> 2, t = lane & 3;
    const int m0 = blockIdx.x * 64, n0 = blockIdx.y * 64;
    const int wm = (wid >> 1) * 32, wn = (wid & 1) * 32;

    const int row = tid >> 1;          // 0..63
    const int half = (tid & 1) * 8;
    const __nv_bfloat16* gAh = xh_hi + (size_t)(m0 + row) * KTOT + INPUT_DIM + half;
    const __nv_bfloat16* gAl = xh_lo + (size_t)(m0 + row) * KTOT + INPUT_DIM + half;
    const __nv_bfloat16* gBh = g_Wdt_hi + (size_t)(n0 + row) * UNITS + half;
    const __nv_bfloat16* gBl = g_Wdt_lo + (size_t)(n0 + row) * UNITS + half;

    float acc[2][4][4];
#pragma unroll
    for (int i = 0; i < 2; i++)
#pragma unroll
        for (int j = 0; j < 4; j++)
#pragma unroll
            for (int l = 0; l < 4; l++) acc[i][j][l] = 0.0f;

    const int NS = UNITS / 16;   // 64
#pragma unroll
    for (int p = 0; p < 2; p++) {
        int kt = p * 16;
        cpa16(smaddr(&sA[p][0][row][half]), gAh + kt);
        cpa16(smaddr(&sA[p][1][row][half]), gAl + kt);
        cpa16(smaddr(&sB[p][0][row][half]), gBh + kt);
        cpa16(smaddr(&sB[p][1][row][half]), gBl + kt);
        cp_commit();
    }

    for (int s = 0; s < NS; s++) {
        asm volatile("cp.async.wait_group 1;\n");
        __syncthreads();

        if (s + 2 < NS) {
            int ps = (s + 2) % 3, kt = (s + 2) * 16;
            cpa16(smaddr(&sA[ps][0][row][half]), gAh + kt);
            cpa16(smaddr(&sA[ps][1][row][half]), gAl + kt);
            cpa16(smaddr(&sB[ps][0][row][half]), gBh + kt);
            cpa16(smaddr(&sB[ps][1][row][half]), gBl + kt);
        }
        cp_commit();

        const int st = s % 3;
        uint32_t ah[2][4], al[2][4];
#pragma unroll
        for (int mt = 0; mt < 2; mt++) {
            int mr = wm + mt * 16;
            ah[mt][0] = ld32s(&sA[st][0][mr + g][2 * t]);
            ah[mt][1] = ld32s(&sA[st][0][mr + g + 8][2 * t]);
            ah[mt][2] = ld32s(&sA[st][0][mr + g][2 * t + 8]);
            ah[mt][3] = ld32s(&sA[st][0][mr + g + 8][2 * t + 8]);
            al[mt][0] = ld32s(&sA[st][1][mr + g][2 * t]);
            al[mt][1] = ld32s(&sA[st][1][mr + g + 8][2 * t]);
            al[mt][2] = ld32s(&sA[st][1][mr + g][2 * t + 8]);
            al[mt][3] = ld32s(&sA[st][1][mr + g + 8][2 * t + 8]);
        }
#pragma unroll
        for (int nt = 0; nt < 4; nt++) {
            int nr = wn + nt * 8 + g;
            uint32_t bh[2], bl[2];
            bh[0] = ld32s(&sB[st][0][nr][2 * t]);
            bh[1] = ld32s(&sB[st][0][nr][2 * t + 8]);
            bl[0] = ld32s(&sB[st][1][nr][2 * t]);
            bl[1] = ld32s(&sB[st][1][nr][2 * t + 8]);
#pragma unroll
            for (int mt = 0; mt < 2; mt++) {
                mma_bf16(acc[mt][nt], ah[mt], bh);
                mma_bf16(acc[mt][nt], ah[mt], bl);
                mma_bf16(acc[mt][nt], al[mt], bh);
            }
        }
    }

    // epilogue: out = acc + bd; also split into next-step x (xh cols 0-255)
#pragma unroll
    for (int mt = 0; mt < 2; mt++) {
#pragma unroll
        for (int nt = 0; nt < 4; nt++) {
            int n = n0 + wn + nt * 8 + 2 * t;
            float bias0 = bd[n], bias1 = bd[n + 1];
#pragma unroll
            for (int rh = 0; rh < 2; rh++) {
                int m = m0 + wm + mt * 16 + g + rh * 8;
                float v0 = acc[mt][nt][rh * 2 + 0] + bias0;
                float v1 = acc[mt][nt][rh * 2 + 1] + bias1;
                *(float2*)&out_t[(size_t)m * OUT_ROW_STRIDE + n] = make_float2(v0, v1);
                __nv_bfloat16 h0, l0, h1, l1;
                split_bf16(v0, &h0, &l0);
                split_bf16(v1, &h1, &l1);
                *(__nv_bfloat162*)&xh_hi_out[(size_t)m * KTOT + n] =
                    __nv_bfloat162(h0, h1);
                *(__nv_bfloat162*)&xh_lo_out[(size_t)m * KTOT + n] =
                    __nv_bfloat162(l0, l1);
            }
        }
    }
}

// ---------------------------------------------------------------------------
extern "C" void kernel_launch(void* const* d_in, const int* in_sizes, int n_in,
                              void* d_out, int out_size)
{
    const float* last_input = (const float*)d_in[0];
    const float* h0 = (const float*)d_in[1];
    const float* c0 = (const float*)d_in[2];
    const float* Wk = (const float*)d_in[3];
    const float* Wr = (const float*)d_in[4];
    const float* bias = (const float*)d_in[5];
    const float* Wd = (const float*)d_in[6];
    const float* bd = (const float*)d_in[7];
    float* out = (float*)d_out;

    float* cbuf;
    __nv_bfloat16 *xh_hi, *xh_lo;
    cudaGetSymbolAddress((void**)&cbuf, g_c);
    cudaGetSymbolAddress((void**)&xh_hi, g_xh_hi);
    cudaGetSymbolAddress((void**)&xh_lo, g_xh_lo);
    const size_t BUF = (size_t)BATCH * KTOT;

    prep_gate_weights<<<(NGATE * KTOT + 255) / 256, 256>>>(Wk, Wr);
    prep_proj_weights<<<(OUT_UNITS * UNITS + 255) / 256, 256>>>(Wd);
    prep_bias<<<(NGATE + 255) / 256, 256>>>(bias);
    prep_x<<<(BATCH * INPUT_DIM + 255) / 256, 256>>>(last_input);
    prep_h<<<(BATCH * UNITS + 255) / 256, 256>>>(h0);

    dim3 gates_grid(BATCH / 128, NGATE / 128);    // (16, 32)
    dim3 proj_grid(BATCH / 64, OUT_UNITS / 64);   // (32, 4)

    for (int t = 0; t < STEPS; ++t) {
        int bi = t & 1, bo = (t + 1) & 1;
        // gates(t): reads buf[bi] (x(t) + h(t-1)), writes h(t) -> buf[bo], c in place
        gates_mma<<<gates_grid, 256>>>(xh_hi + bi * BUF, xh_lo + bi * BUF,
                                       xh_hi + bo * BUF, xh_lo + bo * BUF,
                                       t == 0 ? c0 : cbuf);
        // proj(t): reads h(t) from buf[bo], writes x(t+1) -> buf[bo] + out[:,t,:]
        proj_mma<<<proj_grid, 128>>>(xh_hi + bo * BUF, xh_lo + bo * BUF,
                                     xh_hi + bo * BUF, xh_lo + bo * BUF,
                                     bd, out + (size_t)t * OUT_UNITS);
    }
}